// round 6
// baseline (speedup 1.0000x reference)
#include <cuda_runtime.h>
#include <cuda_bf16.h>
#include <cstdint>

#define BATCH 128
#define SLEN  1024
#define NSENT 64
#define QLEN  64
#define EMB   50
#define RUN   400
#define MEM   300
#define VOC   2000

typedef unsigned long long ull;

__device__ __forceinline__ ull pack2(float lo, float hi) {
    ull r; asm("mov.b64 %0, {%1, %2};" : "=l"(r) : "f"(lo), "f"(hi)); return r;
}
__device__ __forceinline__ ull pdup(float v) { return pack2(v, v); }
__device__ __forceinline__ void fma2(ull& d, ull a, ull b) {
    asm("fma.rn.f32x2 %0, %1, %2, %0;" : "+l"(d) : "l"(a), "l"(b));
}
__device__ __forceinline__ float2 unpack2(ull v) {
    float2 r; asm("mov.b64 {%0, %1}, %2;" : "=f"(r.x), "=f"(r.y) : "l"(v)); return r;
}

// ---------------------------------------------------------------------------
// Device scratch
// ---------------------------------------------------------------------------
__device__ float g_table_i[1024 * 3 * RUN];
__device__ float g_table_q[64 * 3 * RUN];
__device__ float g_hinfo[(size_t)BATCH * SLEN * RUN];
__device__ float g_hq[(size_t)BATCH * QLEN * RUN];
__device__ float g_prod[(size_t)BATCH * NSENT * RUN];
__device__ float g_xzm[(size_t)BATCH * NSENT * 3 * MEM];
__device__ float g_hidden[(size_t)BATCH * NSENT * MEM];
__device__ float g_xza[(size_t)BATCH * NSENT * 3 * VOC];
__device__ float g_rec[(size_t)3 * BATCH * 3 * VOC];       // 3 K-split partials
__device__ float g_hA[(size_t)BATCH * VOC];
__device__ float g_hB[(size_t)BATCH * VOC];

// barrier state: 16 slots, each padded to its own 128B line (32 u32)
__device__ unsigned g_cnt[16 * 32];
__device__ volatile unsigned g_sns[16 * 32];

__device__ __forceinline__ float sigmoidf_(float x) { return 1.f / (1.f + expf(-x)); }

// barrier over G CTAs sharing `slot`; caller keeps per-thread `sense`
__device__ __forceinline__ void group_barrier(int slot, unsigned G, unsigned& sense) {
    __syncthreads();
    sense ^= 1u;
    if (threadIdx.x == 0 && threadIdx.y == 0) {
        __threadfence();
        unsigned prev = atomicAdd(&g_cnt[slot * 32], 1u);
        if (prev == G - 1u) {
            g_cnt[slot * 32] = 0u;
            __threadfence();
            g_sns[slot * 32] = sense;
        } else {
            while (g_sns[slot * 32] != sense) { __nanosleep(64); }
        }
        __threadfence();
    }
    __syncthreads();
}

// ---------------------------------------------------------------------------
// table[v, j] = sum_e emb[v,e] * W[e,j] + b0[j]
// ---------------------------------------------------------------------------
__global__ void build_table_kernel(const float* __restrict__ emb,
                                   const float* __restrict__ W,
                                   const float* __restrict__ b0,
                                   float* __restrict__ table,
                                   int N3) {
    int v = blockIdx.y;
    int j = blockIdx.x * blockDim.x + threadIdx.x;
    __shared__ float se[EMB];
    if (threadIdx.x < EMB) se[threadIdx.x] = emb[(size_t)v * EMB + threadIdx.x];
    __syncthreads();
    if (j < N3) {
        float acc = b0[j];
#pragma unroll 10
        for (int e = 0; e < EMB; ++e) acc += se[e] * W[(size_t)e * N3 + j];
        table[(size_t)v * N3 + j] = acc;
    }
}

// ---------------------------------------------------------------------------
// Persistent GRU, f32x2, per-batch-group barriers (slot = blockIdx.y, G = gridDim.x).
// block (16,8)=128 thr; tile 16 batch x 32 cols.
// ---------------------------------------------------------------------------
template <int H>
__global__ void __launch_bounds__(128, 1)
gru_seq_kernel(const float* __restrict__ xz,
               const int* __restrict__ tok,
               const float* __restrict__ U,
               const float* __restrict__ brec,
               float* __restrict__ hP, float* __restrict__ hQ,
               float* __restrict__ seq_out,
               const int* __restrict__ num_sent,
               int T) {
    extern __shared__ __align__(16) ull smu[];
    ull* su2 = smu;            // [H][48]
    ull* shd = smu + H * 48;   // [16][H]

    const int tx = threadIdx.x;   // 0..15 col-pair
    const int ty = threadIdx.y;   // 0..7 row-group
    const int tid = ty * 16 + tx;
    const int j0 = blockIdx.x * 32;
    const int b0 = blockIdx.y * 16;
    const int N3 = 3 * H;
    const int slot = blockIdx.y;
    const unsigned G = gridDim.x;
    unsigned sense = g_sns[slot * 32];

    for (int e = tid; e < H * 48; e += 128) {
        int k = e / 48, c = e - k * 48;
        int g = c >> 4, p = c & 15;
        int j = j0 + 2 * p;
        float lo = (j < H) ? U[(size_t)k * N3 + g * H + j] : 0.f;
        float hi = (j + 1 < H) ? U[(size_t)k * N3 + g * H + j + 1] : 0.f;
        su2[e] = pack2(lo, hi);
    }
    for (int e = tid; e < 16 * 32; e += 128) {
        int bb = e >> 5, jj = e & 31;
        if (j0 + jj < H) hP[(size_t)(b0 + bb) * H + j0 + jj] = 0.f;
    }
    group_barrier(slot, G, sense);

    float* hp = hP;
    float* hn = hQ;

    const int jA = j0 + 2 * tx;
    const int jB = jA + 1;
    float bzA = 0, brA = 0, bhA = 0, bzB = 0, brB = 0, bhB = 0;
    if (jA < H) { bzA = brec[jA]; brA = brec[H + jA]; bhA = brec[2 * H + jA]; }
    if (jB < H) { bzB = brec[jB]; brB = brec[H + jB]; bhB = brec[2 * H + jB]; }

    const ull* up = su2 + tx;

    for (int t = 0; t < T; ++t) {
        // stage h_prev rows, duplicated (no runtime div)
#pragma unroll
        for (int row = 0; row < 16; ++row) {
            const float* src = hp + (size_t)(b0 + row) * H;
            ull* dst = shd + row * H;
            for (int k = tid; k < H; k += 128)
                dst[k] = pdup(src[k]);
        }
        __syncthreads();

        ull az0 = 0, az1 = 0, ar0 = 0, ar1 = 0, ah0 = 0, ah1 = 0;
        const ull* h0p = shd + (2 * ty) * H;
        const ull* h1p = shd + (2 * ty + 1) * H;
#pragma unroll 8
        for (int k = 0; k < H; ++k) {
            ull uz = up[k * 48];
            ull ur = up[k * 48 + 16];
            ull uh = up[k * 48 + 32];
            ull h0 = h0p[k];
            ull h1 = h1p[k];
            fma2(az0, h0, uz); fma2(az1, h1, uz);
            fma2(ar0, h0, ur); fma2(ar1, h1, ur);
            fma2(ah0, h0, uh); fma2(ah1, h1, uh);
        }

#pragma unroll
        for (int r = 0; r < 2; ++r) {
            const int row = 2 * ty + r;
            const int b = b0 + row;
            const float* xrow;
            if (tok) xrow = xz + (size_t)tok[(size_t)b * T + t] * N3;
            else     xrow = xz + ((size_t)b * T + t) * N3;
            float2 AZ = unpack2(r ? az1 : az0);
            float2 AR = unpack2(r ? ar1 : ar0);
            float2 AH = unpack2(r ? ah1 : ah0);
            float padv = 1.f;
            if (num_sent) padv = (t <= num_sent[b]) ? 1.f : 0.f;
            if (jA < H) {
                float z  = sigmoidf_(xrow[jA] + AZ.x + bzA);
                float rr = sigmoidf_(xrow[H + jA] + AR.x + brA);
                float hh = tanhf(xrow[2 * H + jA] + rr * (AH.x + bhA));
                float hprev = unpack2(shd[row * H + jA]).x;
                float hnew = z * hprev + (1.f - z) * hh;
                hn[(size_t)b * H + jA] = hnew;
                seq_out[((size_t)b * T + t) * H + jA] = hnew * padv;
            }
            if (jB < H) {
                float z  = sigmoidf_(xrow[jB] + AZ.y + bzB);
                float rr = sigmoidf_(xrow[H + jB] + AR.y + brB);
                float hh = tanhf(xrow[2 * H + jB] + rr * (AH.y + bhB));
                float hprev = unpack2(shd[row * H + jB]).x;
                float hnew = z * hprev + (1.f - z) * hh;
                hn[(size_t)b * H + jB] = hnew;
                seq_out[((size_t)b * T + t) * H + jB] = hnew * padv;
            }
        }
        group_barrier(slot, G, sense);
        float* tmp = hp; hp = hn; hn = tmp;
    }
}

// ---------------------------------------------------------------------------
// prod
// ---------------------------------------------------------------------------
__global__ void prod_kernel(const float* __restrict__ hinfo,
                            const float* __restrict__ hq,
                            const int* __restrict__ info_idx,
                            const int* __restrict__ num_sent,
                            const int* __restrict__ qidx,
                            float* __restrict__ prod) {
    const int nn = blockIdx.x;
    const int b  = blockIdx.y;
    const int si = info_idx[b * NSENT + nn];
    const int qi = qidx[b] - 1;
    const float padv = (nn <= num_sent[b]) ? 1.f : 0.f;
    const float* hi  = hinfo + ((size_t)b * SLEN + si) * RUN;
    const float* hqr = hq + ((size_t)b * QLEN + qi) * RUN;
    float* pr = prod + ((size_t)b * NSENT + nn) * RUN;
    for (int jj = threadIdx.x; jj < RUN; jj += blockDim.x)
        pr[jj] = hi[jj] * hqr[jj] * padv;
}

// ---------------------------------------------------------------------------
// Generic C = A@W + bias, 64x64 tile, BK=16, 4x4/thread. (xzm, xza)
// ---------------------------------------------------------------------------
__global__ void gemm_bias_kernel(const float* __restrict__ A,
                                 const float* __restrict__ W,
                                 const float* __restrict__ bias,
                                 float* __restrict__ C,
                                 int Mdim, int Kdim, int Ndim) {
    __shared__ __align__(16) float As[16][68];
    __shared__ __align__(16) float Bs[16][68];
    const int tid = threadIdx.x;
    const int tx = tid & 15;
    const int ty = tid >> 4;
    const int m0 = blockIdx.y * 64;
    const int n0 = blockIdx.x * 64;

    float acc[4][4];
#pragma unroll
    for (int i = 0; i < 4; ++i)
#pragma unroll
        for (int jj = 0; jj < 4; ++jj) acc[i][jj] = 0.f;

    for (int k0 = 0; k0 < Kdim; k0 += 16) {
        for (int e = tid; e < 1024; e += 256) {
            int mm = e >> 4, kk = e & 15;
            int m = m0 + mm, k = k0 + kk;
            As[kk][mm] = (m < Mdim && k < Kdim) ? A[(size_t)m * Kdim + k] : 0.f;
        }
        for (int e = tid; e < 1024; e += 256) {
            int kk = e >> 6, nn = e & 63;
            int k = k0 + kk, nv = n0 + nn;
            Bs[kk][nn] = (k < Kdim && nv < Ndim) ? W[(size_t)k * Ndim + nv] : 0.f;
        }
        __syncthreads();
#pragma unroll
        for (int kk = 0; kk < 16; ++kk) {
            float4 a4 = *reinterpret_cast<const float4*>(&As[kk][ty * 4]);
            float4 b4 = *reinterpret_cast<const float4*>(&Bs[kk][tx * 4]);
            float av[4] = {a4.x, a4.y, a4.z, a4.w};
            float bv[4] = {b4.x, b4.y, b4.z, b4.w};
#pragma unroll
            for (int i = 0; i < 4; ++i)
#pragma unroll
                for (int jj = 0; jj < 4; ++jj) acc[i][jj] += av[i] * bv[jj];
        }
        __syncthreads();
    }
#pragma unroll
    for (int i = 0; i < 4; ++i) {
        int m = m0 + ty * 4 + i;
        if (m >= Mdim) continue;
#pragma unroll
        for (int jj = 0; jj < 4; ++jj) {
            int nv = n0 + tx * 4 + jj;
            if (nv < Ndim) C[(size_t)m * Ndim + nv] = acc[i][jj] + bias[nv];
        }
    }
}

// ---------------------------------------------------------------------------
// Persistent answer GRU. grid = 141 CTAs (47 N-tiles x 3 K-splits), 256 thr.
// B reads restructured conflict-free: lane tn reads columns {tn,tn+16,tn+32,tn+48}.
// ---------------------------------------------------------------------------
#define ANS_G    141
#define NTILE_N  47
#define KSPLIT_W 672
#define KCH      21
#define REC_OFF  ((size_t)BATCH * 3 * VOC)
#define ANS_SLOT 15

__global__ void __launch_bounds__(256, 1)
answer_kernel(const float* __restrict__ xza,
              const float* __restrict__ Ua,
              const float* __restrict__ ba1,
              float* __restrict__ rec,
              float* __restrict__ hP, float* __restrict__ hQ,
              float* __restrict__ out) {
    extern __shared__ __align__(16) char asmem[];
    float* AsBuf = (float*)asmem;                               // 2*4160 floats
    ull*   BnBuf = (ull*)(asmem + 2 * 4160 * sizeof(float));    // 2*2048 ull
    ull*   BwBuf = BnBuf + 2 * 2048;                            // 2*2048 ull
    __shared__ float red[256];

    const int tid = threadIdx.x;
    const unsigned G = gridDim.x;
    unsigned sense = g_sns[ANS_SLOT * 32];

    for (int e = blockIdx.x * 256 + tid; e < BATCH * VOC; e += G * 256)
        hP[e] = 0.f;
    group_barrier(ANS_SLOT, G, sense);

    float* hp = hP;
    float* hn = hQ;

    const int ks    = blockIdx.x / NTILE_N;
    const int ntile = blockIdx.x - ks * NTILE_N;
    const int n0    = ntile * 128;
    const int kbase = ks * KSPLIT_W;
    float* recK = rec + (size_t)ks * REC_OFF;

    const int tm = tid >> 4;    // 0..15 -> rows tm*8..tm*8+7
    const int tn = tid & 15;    // 0..15 -> col-pairs {tn, tn+16, tn+32, tn+48}

    const int akk = tid & 15;
    const int amm0 = tid >> 4;

    for (int n = 0; n < NSENT; ++n) {
        // ================= phase A =================
        {
            ull aD[16], aX[16];
#pragma unroll
            for (int i = 0; i < 16; ++i) { aD[i] = 0ull; aX[i] = 0ull; }

            {
                const int k0 = kbase;
#pragma unroll
                for (int p = 0; p < 16; ++p) {
                    int e = p * 256 + tid;
                    int mm = e >> 5, kk = e & 31;
                    int k = k0 + kk;
                    AsBuf[kk * 130 + mm] = (k < VOC) ? hp[(size_t)mm * VOC + k] : 0.f;
                }
#pragma unroll
                for (int p = 0; p < 8; ++p) {
                    int e = p * 256 + tid;
                    int kk = e >> 6, np = e & 63;
                    int k = k0 + kk, nc = n0 + 2 * np;
                    float lo = 0.f, hi = 0.f;
                    if (k < VOC && nc < 3 * VOC) {
                        float2 v = *reinterpret_cast<const float2*>(&Ua[(size_t)k * (3 * VOC) + nc]);
                        lo = v.x; hi = v.y;
                    }
                    BnBuf[kk * 64 + np] = pack2(lo, hi);
                    BwBuf[kk * 64 + np] = pack2(hi, lo);
                }
            }

            int cur = 0;
            for (int ch = 0; ch < KCH; ++ch) {
                __syncthreads();
                if (ch + 1 < KCH) {
                    const int k0 = kbase + (ch + 1) * 32;
                    const int nb = cur ^ 1;
                    float* Asn = AsBuf + nb * 4160;
                    ull*   Bnn = BnBuf + nb * 2048;
                    ull*   Bwn = BwBuf + nb * 2048;
#pragma unroll
                    for (int p = 0; p < 16; ++p) {
                        int e = p * 256 + tid;
                        int mm = e >> 5, kk = e & 31;
                        int k = k0 + kk;
                        Asn[kk * 130 + mm] = (k < VOC) ? hp[(size_t)mm * VOC + k] : 0.f;
                    }
#pragma unroll
                    for (int p = 0; p < 8; ++p) {
                        int e = p * 256 + tid;
                        int kk = e >> 6, np = e & 63;
                        int k = k0 + kk, nc = n0 + 2 * np;
                        float lo = 0.f, hi = 0.f;
                        if (k < VOC && nc < 3 * VOC) {
                            float2 v = *reinterpret_cast<const float2*>(&Ua[(size_t)k * (3 * VOC) + nc]);
                            lo = v.x; hi = v.y;
                        }
                        Bnn[kk * 64 + np] = pack2(lo, hi);
                        Bwn[kk * 64 + np] = pack2(hi, lo);
                    }
                }
                const float* Asb = AsBuf + cur * 4160 + tm * 8;
                const ull*   Bnb = BnBuf + cur * 2048 + tn;
                const ull*   Bwb = BwBuf + cur * 2048 + tn;
#pragma unroll 4
                for (int kk = 0; kk < 32; ++kk) {
                    const float* ap = Asb + kk * 130;
                    ull a0 = *reinterpret_cast<const ull*>(ap + 0);
                    ull a1 = *reinterpret_cast<const ull*>(ap + 2);
                    ull a2 = *reinterpret_cast<const ull*>(ap + 4);
                    ull a3 = *reinterpret_cast<const ull*>(ap + 6);
                    const ull* bp = Bnb + kk * 64;
                    const ull* wp = Bwb + kk * 64;
                    // conflict-free: lane tn reads ull at tn, tn+16, tn+32, tn+48
                    ull b0 = bp[0],  b1 = bp[16], b2 = bp[32], b3 = bp[48];
                    ull w0 = wp[0],  w1 = wp[16], w2 = wp[32], w3 = wp[48];
                    fma2(aD[0],  a0, b0); fma2(aX[0],  a0, w0);
                    fma2(aD[1],  a0, b1); fma2(aX[1],  a0, w1);
                    fma2(aD[2],  a0, b2); fma2(aX[2],  a0, w2);
                    fma2(aD[3],  a0, b3); fma2(aX[3],  a0, w3);
                    fma2(aD[4],  a1, b0); fma2(aX[4],  a1, w0);
                    fma2(aD[5],  a1, b1); fma2(aX[5],  a1, w1);
                    fma2(aD[6],  a1, b2); fma2(aX[6],  a1, w2);
                    fma2(aD[7],  a1, b3); fma2(aX[7],  a1, w3);
                    fma2(aD[8],  a2, b0); fma2(aX[8],  a2, w0);
                    fma2(aD[9],  a2, b1); fma2(aX[9],  a2, w1);
                    fma2(aD[10], a2, b2); fma2(aX[10], a2, w2);
                    fma2(aD[11], a2, b3); fma2(aX[11], a2, w3);
                    fma2(aD[12], a3, b0); fma2(aX[12], a3, w0);
                    fma2(aD[13], a3, b1); fma2(aX[13], a3, w1);
                    fma2(aD[14], a3, b2); fma2(aX[14], a3, w2);
                    fma2(aD[15], a3, b3); fma2(aX[15], a3, w3);
                }
                cur ^= 1;
            }
            __syncthreads();
#pragma unroll
            for (int mi = 0; mi < 4; ++mi) {
#pragma unroll
                for (int ni = 0; ni < 4; ++ni) {
                    int m  = tm * 8 + 2 * mi;
                    int nc = n0 + 2 * (tn + 16 * ni);
                    if (nc < 3 * VOC) {
                        float2 d = unpack2(aD[mi * 4 + ni]);
                        float2 x = unpack2(aX[mi * 4 + ni]);
                        *reinterpret_cast<ull*>(&recK[(size_t)m * (3 * VOC) + nc]) = pack2(d.x, x.x);
                        *reinterpret_cast<ull*>(&recK[(size_t)(m + 1) * (3 * VOC) + nc]) = pack2(x.y, d.y);
                    }
                }
            }
        }
        group_barrier(ANS_SLOT, G, sense);

        // ================= phase B =================
        if (blockIdx.x < BATCH) {
            const int b = blockIdx.x;
            const float* xrow = xza + ((size_t)b * NSENT + n) * (3 * VOC);
            const float* r0 = rec + (size_t)b * (3 * VOC);
            const float* r1 = r0 + REC_OFF;
            const float* r2 = r1 + REC_OFF;
            float zv[8], tv[8];
            float m = -1e30f;
#pragma unroll
            for (int i = 0; i < 8; ++i) {
                int jj = tid + i * 256;
                if (jj < VOC) {
                    float Rz = r0[jj] + r1[jj] + r2[jj] + ba1[jj];
                    float Rr = r0[VOC + jj] + r1[VOC + jj] + r2[VOC + jj] + ba1[VOC + jj];
                    float Rh = r0[2 * VOC + jj] + r1[2 * VOC + jj] + r2[2 * VOC + jj] + ba1[2 * VOC + jj];
                    float z = sigmoidf_(xrow[jj] + Rz);
                    float r = sigmoidf_(xrow[VOC + jj] + Rr);
                    float t = xrow[2 * VOC + jj] + r * Rh;
                    zv[i] = z; tv[i] = t;
                    m = fmaxf(m, t);
                } else { zv[i] = 0.f; tv[i] = -1e30f; }
            }
            red[tid] = m; __syncthreads();
            for (int s = 128; s > 0; s >>= 1) {
                if (tid < s) red[tid] = fmaxf(red[tid], red[tid + s]);
                __syncthreads();
            }
            m = red[0]; __syncthreads();

            float ev[8];
            float sum = 0.f;
#pragma unroll
            for (int i = 0; i < 8; ++i) {
                int jj = tid + i * 256;
                if (jj < VOC) { ev[i] = expf(tv[i] - m); sum += ev[i]; }
                else ev[i] = 0.f;
            }
            red[tid] = sum; __syncthreads();
            for (int s = 128; s > 0; s >>= 1) {
                if (tid < s) red[tid] += red[tid + s];
                __syncthreads();
            }
            const float inv = 1.f / red[0];
            __syncthreads();

#pragma unroll
            for (int i = 0; i < 8; ++i) {
                int jj = tid + i * 256;
                if (jj < VOC) {
                    float hh = ev[i] * inv;
                    float z  = zv[i];
                    float hprev = hp[(size_t)b * VOC + jj];
                    float hnew = z * hprev + (1.f - z) * hh;
                    hn[(size_t)b * VOC + jj] = hnew;
                    out[((size_t)b * NSENT + n) * VOC + jj] = hnew;
                }
            }
        }
        group_barrier(ANS_SLOT, G, sense);
        float* tmp = hp; hp = hn; hn = tmp;
    }
}

// ---------------------------------------------------------------------------
// Host orchestration
// ---------------------------------------------------------------------------
extern "C" void kernel_launch(void* const* d_in, const int* in_sizes, int n_in,
                              void* d_out, int out_size) {
    const int*   info      = (const int*)d_in[0];
    const int*   info_idx  = (const int*)d_in[1];
    const int*   num_sent  = (const int*)d_in[2];
    const int*   question  = (const int*)d_in[3];
    const int*   qidx      = (const int*)d_in[4];
    const float* info_emb  = (const float*)d_in[5];
    const float* Wi        = (const float*)d_in[6];
    const float* Ui        = (const float*)d_in[7];
    const float* bi        = (const float*)d_in[8];
    const float* q_emb     = (const float*)d_in[9];
    const float* Wq        = (const float*)d_in[10];
    const float* Uq        = (const float*)d_in[11];
    const float* bq        = (const float*)d_in[12];
    const float* Wm        = (const float*)d_in[13];
    const float* Um        = (const float*)d_in[14];
    const float* bm        = (const float*)d_in[15];
    const float* Wa        = (const float*)d_in[16];
    const float* Ua        = (const float*)d_in[17];
    const float* ba        = (const float*)d_in[18];
    float* out = (float*)d_out;

    float *tbl_i, *tbl_q, *hinfo, *hq, *prod, *xzm, *hidden, *xza, *rec, *hA, *hB;
    cudaGetSymbolAddress((void**)&tbl_i, g_table_i);
    cudaGetSymbolAddress((void**)&tbl_q, g_table_q);
    cudaGetSymbolAddress((void**)&hinfo, g_hinfo);
    cudaGetSymbolAddress((void**)&hq, g_hq);
    cudaGetSymbolAddress((void**)&prod, g_prod);
    cudaGetSymbolAddress((void**)&xzm, g_xzm);
    cudaGetSymbolAddress((void**)&hidden, g_hidden);
    cudaGetSymbolAddress((void**)&xza, g_xza);
    cudaGetSymbolAddress((void**)&rec, g_rec);
    cudaGetSymbolAddress((void**)&hA, g_hA);
    cudaGetSymbolAddress((void**)&hB, g_hB);

    const size_t ansSmem = 2 * 4160 * sizeof(float) + 4 * 2048 * sizeof(ull);
    const size_t smemR = ((size_t)RUN * 48 + (size_t)16 * RUN) * 8;   // 204800
    const size_t smemM = ((size_t)MEM * 48 + (size_t)16 * MEM) * 8;   // 153600

    static bool attr_set = false;
    if (!attr_set) {
        cudaFuncSetAttribute(gru_seq_kernel<RUN>,
                             cudaFuncAttributeMaxDynamicSharedMemorySize, (int)smemR);
        cudaFuncSetAttribute(gru_seq_kernel<MEM>,
                             cudaFuncAttributeMaxDynamicSharedMemorySize, (int)smemM);
        cudaFuncSetAttribute(answer_kernel,
                             cudaFuncAttributeMaxDynamicSharedMemorySize, (int)ansSmem);
        attr_set = true;
    }

    build_table_kernel<<<dim3((3 * RUN + 255) / 256, 1024), 256>>>(info_emb, Wi, bi, tbl_i, 3 * RUN);
    build_table_kernel<<<dim3((3 * RUN + 255) / 256, 64), 256>>>(q_emb, Wq, bq, tbl_q, 3 * RUN);

    const dim3 blk(16, 8);

    // info GRU (T=1024, H=400): 13x8 = 104 CTAs, barriers per batch group (13 CTAs)
    gru_seq_kernel<RUN><<<dim3((RUN + 31) / 32, 8), blk, smemR>>>(
        tbl_i, info, Ui, bi + 3 * RUN, hA, hB, hinfo, nullptr, SLEN);

    // question GRU (T=64, H=400)
    gru_seq_kernel<RUN><<<dim3((RUN + 31) / 32, 8), blk, smemR>>>(
        tbl_q, question, Uq, bq + 3 * RUN, hA, hB, hq, nullptr, QLEN);

    prod_kernel<<<dim3(NSENT, BATCH), 128>>>(hinfo, hq, info_idx, num_sent, qidx, prod);

    gemm_bias_kernel<<<dim3((3 * MEM + 63) / 64, (BATCH * NSENT) / 64), 256>>>(
        prod, Wm, bm, xzm, BATCH * NSENT, RUN, 3 * MEM);

    // memory GRU (T=64, H=300): 10x8 = 80 CTAs
    gru_seq_kernel<MEM><<<dim3((MEM + 31) / 32, 8), blk, smemM>>>(
        xzm, nullptr, Um, bm + 3 * MEM, hA, hB, hidden, num_sent, NSENT);

    gemm_bias_kernel<<<dim3((3 * VOC + 63) / 64, (BATCH * NSENT) / 64), 256>>>(
        hidden, Wa, ba, xza, BATCH * NSENT, MEM, 3 * VOC);

    answer_kernel<<<ANS_G, 256, ansSmem>>>(xza, Ua, ba + 3 * VOC, rec, hA, hB, out);
}

// round 7
// speedup vs baseline: 1.5839x; 1.5839x over previous
#include <cuda_runtime.h>
#include <cuda_bf16.h>
#include <cstdint>
#include <cstdio>

#define BATCH 128
#define SLEN  1024
#define NSENT 64
#define QLEN  64
#define EMB   50
#define RUN   400
#define MEM   300
#define VOC   2000

typedef unsigned long long ull;

__device__ __forceinline__ ull pack2(float lo, float hi) {
    ull r; asm("mov.b64 %0, {%1, %2};" : "=l"(r) : "f"(lo), "f"(hi)); return r;
}
__device__ __forceinline__ ull pdup(float v) { return pack2(v, v); }
__device__ __forceinline__ void fma2(ull& d, ull a, ull b) {
    asm("fma.rn.f32x2 %0, %1, %2, %0;" : "+l"(d) : "l"(a), "l"(b));
}
__device__ __forceinline__ void add2(ull& d, ull a) {
    asm("add.rn.f32x2 %0, %0, %1;" : "+l"(d) : "l"(a));
}
__device__ __forceinline__ float2 unpack2(ull v) {
    float2 r; asm("mov.b64 {%0, %1}, %2;" : "=f"(r.x), "=f"(r.y) : "l"(v)); return r;
}

// ---------------------------------------------------------------------------
// Device scratch
// ---------------------------------------------------------------------------
__device__ float g_table_i[1024 * 3 * RUN];
__device__ float g_table_q[64 * 3 * RUN];
__device__ float g_hinfo[(size_t)BATCH * SLEN * RUN];
__device__ float g_hq[(size_t)BATCH * QLEN * RUN];
__device__ float g_prod[(size_t)BATCH * NSENT * RUN];
__device__ float g_xzm[(size_t)BATCH * NSENT * 3 * MEM];
__device__ float g_hidden[(size_t)BATCH * NSENT * MEM];
__device__ float g_xza[(size_t)BATCH * NSENT * 3 * VOC];
__device__ float g_rec[(size_t)3 * BATCH * 3 * VOC];
__device__ float g_hA[(size_t)BATCH * VOC];
__device__ float g_hB[(size_t)BATCH * VOC];

// barrier state: 16 slots, each on its own 128B line
__device__ unsigned g_cnt[16 * 32];
__device__ volatile unsigned g_sns[16 * 32];

// phase timestamps (globaltimer ns)
__device__ unsigned long long g_ts[16];

__device__ __forceinline__ float sigmoidf_(float x) { return 1.f / (1.f + expf(-x)); }

// barrier over G CTAs sharing `slot`; pure spin, no nanosleep
__device__ __forceinline__ void group_barrier(int slot, unsigned G, unsigned& sense) {
    __syncthreads();
    sense ^= 1u;
    if (threadIdx.x == 0 && threadIdx.y == 0 && threadIdx.z == 0) {
        __threadfence();
        unsigned prev = atomicAdd(&g_cnt[slot * 32], 1u);
        if (prev == G - 1u) {
            g_cnt[slot * 32] = 0u;
            __threadfence();
            g_sns[slot * 32] = sense;
        } else {
            while (g_sns[slot * 32] != sense) { }
        }
        __threadfence();
    }
    __syncthreads();
}

// ---------------------------------------------------------------------------
// timing stamps
// ---------------------------------------------------------------------------
__global__ void stamp_kernel(int i) {
    unsigned long long t;
    asm volatile("mov.u64 %0, %%globaltimer;" : "=l"(t));
    g_ts[i] = t;
}
__global__ void report_kernel() {
    printf("PHASES(us) tbl=%.0f info=%.0f q=%.0f prod=%.0f xzm=%.0f mem=%.0f xza=%.0f ans=%.0f\n",
           (g_ts[1] - g_ts[0]) * 1e-3, (g_ts[2] - g_ts[1]) * 1e-3,
           (g_ts[3] - g_ts[2]) * 1e-3, (g_ts[4] - g_ts[3]) * 1e-3,
           (g_ts[5] - g_ts[4]) * 1e-3, (g_ts[6] - g_ts[5]) * 1e-3,
           (g_ts[7] - g_ts[6]) * 1e-3, (g_ts[8] - g_ts[7]) * 1e-3);
}

// ---------------------------------------------------------------------------
// table[v, j] = sum_e emb[v,e] * W[e,j] + b0[j]
// ---------------------------------------------------------------------------
__global__ void build_table_kernel(const float* __restrict__ emb,
                                   const float* __restrict__ W,
                                   const float* __restrict__ b0,
                                   float* __restrict__ table,
                                   int N3) {
    int v = blockIdx.y;
    int j = blockIdx.x * blockDim.x + threadIdx.x;
    __shared__ float se[EMB];
    if (threadIdx.x < EMB) se[threadIdx.x] = emb[(size_t)v * EMB + threadIdx.x];
    __syncthreads();
    if (j < N3) {
        float acc = b0[j];
#pragma unroll 10
        for (int e = 0; e < EMB; ++e) acc += se[e] * W[(size_t)e * N3 + j];
        table[(size_t)v * N3 + j] = acc;
    }
}

// ---------------------------------------------------------------------------
// Persistent GRU, f32x2, 2-way k-split. block (16,8,2)=256 thr.
// Tile 16 batch x 32 cols; thread (tx,ty,tz): rows {2ty,2ty+1}, col-pair tx,
// k in [tz*H/2, (tz+1)*H/2). tz=1 dumps partials to smem; tz=0 reduces+gates.
// ---------------------------------------------------------------------------
template <int H>
__global__ void __launch_bounds__(256, 1)
gru_seq_kernel(const float* __restrict__ xz,
               const int* __restrict__ tok,
               const float* __restrict__ U,
               const float* __restrict__ brec,
               float* __restrict__ hP, float* __restrict__ hQ,
               float* __restrict__ seq_out,
               const int* __restrict__ num_sent,
               int T) {
    extern __shared__ __align__(16) ull smu[];
    ull* su2 = smu;            // [H][48]
    ull* shd = smu + H * 48;   // [16][H]
    __shared__ ull sred[128 * 6];

    const int tx = threadIdx.x;   // 0..15 col-pair
    const int ty = threadIdx.y;   // 0..7 row-group
    const int tz = threadIdx.z;   // 0..1 k-split
    const int tid128 = ty * 16 + tx;
    const int tid = tz * 128 + tid128;
    const int j0 = blockIdx.x * 32;
    const int b0 = blockIdx.y * 16;
    const int N3 = 3 * H;
    const int slot = blockIdx.y;
    const unsigned G = gridDim.x;
    unsigned sense = g_sns[slot * 32];

    for (int e = tid; e < H * 48; e += 256) {
        int k = e / 48, c = e - k * 48;
        int g = c >> 4, p = c & 15;
        int j = j0 + 2 * p;
        float lo = (j < H) ? U[(size_t)k * N3 + g * H + j] : 0.f;
        float hi = (j + 1 < H) ? U[(size_t)k * N3 + g * H + j + 1] : 0.f;
        su2[e] = pack2(lo, hi);
    }
    for (int e = tid; e < 16 * 32; e += 256) {
        int bb = e >> 5, jj = e & 31;
        if (j0 + jj < H) hP[(size_t)(b0 + bb) * H + j0 + jj] = 0.f;
    }
    group_barrier(slot, G, sense);

    float* hp = hP;
    float* hn = hQ;

    const int jA = j0 + 2 * tx;
    const int jB = jA + 1;
    float bzA = 0, brA = 0, bhA = 0, bzB = 0, brB = 0, bhB = 0;
    if (jA < H) { bzA = brec[jA]; brA = brec[H + jA]; bhA = brec[2 * H + jA]; }
    if (jB < H) { bzB = brec[jB]; brB = brec[H + jB]; bhB = brec[2 * H + jB]; }

    constexpr int Hh = H / 2;
    const int kBeg = tz * Hh;
    const ull* up = su2 + tx;

    for (int t = 0; t < T; ++t) {
        // stage h_prev rows, duplicated (flat loop, compile-time /H)
        for (int e = tid; e < 16 * H; e += 256) {
            int row = e / H, k = e - row * H;
            shd[row * H + k] = pdup(hp[(size_t)(b0 + row) * H + k]);
        }
        __syncthreads();

        ull az0 = 0, az1 = 0, ar0 = 0, ar1 = 0, ah0 = 0, ah1 = 0;
        const ull* h0p = shd + (2 * ty) * H;
        const ull* h1p = shd + (2 * ty + 1) * H;
#pragma unroll 4
        for (int kk = 0; kk < Hh; ++kk) {
            const int k = kBeg + kk;
            ull uz = up[k * 48];
            ull ur = up[k * 48 + 16];
            ull uh = up[k * 48 + 32];
            ull h0 = h0p[k];
            ull h1 = h1p[k];
            fma2(az0, h0, uz); fma2(az1, h1, uz);
            fma2(ar0, h0, ur); fma2(ar1, h1, ur);
            fma2(ah0, h0, uh); fma2(ah1, h1, uh);
        }

        if (tz == 1) {
            ull* s = sred + tid128 * 6;
            s[0] = az0; s[1] = az1; s[2] = ar0; s[3] = ar1; s[4] = ah0; s[5] = ah1;
        }
        __syncthreads();

        if (tz == 0) {
            const ull* s = sred + tid128 * 6;
            add2(az0, s[0]); add2(az1, s[1]);
            add2(ar0, s[2]); add2(ar1, s[3]);
            add2(ah0, s[4]); add2(ah1, s[5]);

#pragma unroll
            for (int r = 0; r < 2; ++r) {
                const int row = 2 * ty + r;
                const int b = b0 + row;
                const float* xrow;
                if (tok) xrow = xz + (size_t)tok[(size_t)b * T + t] * N3;
                else     xrow = xz + ((size_t)b * T + t) * N3;
                float2 AZ = unpack2(r ? az1 : az0);
                float2 AR = unpack2(r ? ar1 : ar0);
                float2 AH = unpack2(r ? ah1 : ah0);
                float padv = 1.f;
                if (num_sent) padv = (t <= num_sent[b]) ? 1.f : 0.f;
                if (jA < H) {
                    float z  = sigmoidf_(xrow[jA] + AZ.x + bzA);
                    float rr = sigmoidf_(xrow[H + jA] + AR.x + brA);
                    float hh = tanhf(xrow[2 * H + jA] + rr * (AH.x + bhA));
                    float hprev = unpack2(shd[row * H + jA]).x;
                    float hnew = z * hprev + (1.f - z) * hh;
                    hn[(size_t)b * H + jA] = hnew;
                    seq_out[((size_t)b * T + t) * H + jA] = hnew * padv;
                }
                if (jB < H) {
                    float z  = sigmoidf_(xrow[jB] + AZ.y + bzB);
                    float rr = sigmoidf_(xrow[H + jB] + AR.y + brB);
                    float hh = tanhf(xrow[2 * H + jB] + rr * (AH.y + bhB));
                    float hprev = unpack2(shd[row * H + jB]).x;
                    float hnew = z * hprev + (1.f - z) * hh;
                    hn[(size_t)b * H + jB] = hnew;
                    seq_out[((size_t)b * T + t) * H + jB] = hnew * padv;
                }
            }
        }
        group_barrier(slot, G, sense);
        float* tmp = hp; hp = hn; hn = tmp;
    }
}

// ---------------------------------------------------------------------------
// prod
// ---------------------------------------------------------------------------
__global__ void prod_kernel(const float* __restrict__ hinfo,
                            const float* __restrict__ hq,
                            const int* __restrict__ info_idx,
                            const int* __restrict__ num_sent,
                            const int* __restrict__ qidx,
                            float* __restrict__ prod) {
    const int nn = blockIdx.x;
    const int b  = blockIdx.y;
    const int si = info_idx[b * NSENT + nn];
    const int qi = qidx[b] - 1;
    const float padv = (nn <= num_sent[b]) ? 1.f : 0.f;
    const float* hi  = hinfo + ((size_t)b * SLEN + si) * RUN;
    const float* hqr = hq + ((size_t)b * QLEN + qi) * RUN;
    float* pr = prod + ((size_t)b * NSENT + nn) * RUN;
    for (int jj = threadIdx.x; jj < RUN; jj += blockDim.x)
        pr[jj] = hi[jj] * hqr[jj] * padv;
}

// ---------------------------------------------------------------------------
// Generic C = A@W + bias, 64x64 tile, BK=16, 4x4/thread. (xzm, xza)
// ---------------------------------------------------------------------------
__global__ void gemm_bias_kernel(const float* __restrict__ A,
                                 const float* __restrict__ W,
                                 const float* __restrict__ bias,
                                 float* __restrict__ C,
                                 int Mdim, int Kdim, int Ndim) {
    __shared__ __align__(16) float As[16][68];
    __shared__ __align__(16) float Bs[16][68];
    const int tid = threadIdx.x;
    const int tx = tid & 15;
    const int ty = tid >> 4;
    const int m0 = blockIdx.y * 64;
    const int n0 = blockIdx.x * 64;

    float acc[4][4];
#pragma unroll
    for (int i = 0; i < 4; ++i)
#pragma unroll
        for (int jj = 0; jj < 4; ++jj) acc[i][jj] = 0.f;

    for (int k0 = 0; k0 < Kdim; k0 += 16) {
        for (int e = tid; e < 1024; e += 256) {
            int mm = e >> 4, kk = e & 15;
            int m = m0 + mm, k = k0 + kk;
            As[kk][mm] = (m < Mdim && k < Kdim) ? A[(size_t)m * Kdim + k] : 0.f;
        }
        for (int e = tid; e < 1024; e += 256) {
            int kk = e >> 6, nn = e & 63;
            int k = k0 + kk, nv = n0 + nn;
            Bs[kk][nn] = (k < Kdim && nv < Ndim) ? W[(size_t)k * Ndim + nv] : 0.f;
        }
        __syncthreads();
#pragma unroll
        for (int kk = 0; kk < 16; ++kk) {
            float4 a4 = *reinterpret_cast<const float4*>(&As[kk][ty * 4]);
            float4 b4 = *reinterpret_cast<const float4*>(&Bs[kk][tx * 4]);
            float av[4] = {a4.x, a4.y, a4.z, a4.w};
            float bv[4] = {b4.x, b4.y, b4.z, b4.w};
#pragma unroll
            for (int i = 0; i < 4; ++i)
#pragma unroll
                for (int jj = 0; jj < 4; ++jj) acc[i][jj] += av[i] * bv[jj];
        }
        __syncthreads();
    }
#pragma unroll
    for (int i = 0; i < 4; ++i) {
        int m = m0 + ty * 4 + i;
        if (m >= Mdim) continue;
#pragma unroll
        for (int jj = 0; jj < 4; ++jj) {
            int nv = n0 + tx * 4 + jj;
            if (nv < Ndim) C[(size_t)m * Ndim + nv] = acc[i][jj] + bias[nv];
        }
    }
}

// ---------------------------------------------------------------------------
// Persistent answer GRU. grid = 141 CTAs (47 N-tiles x 3 K-splits), 256 thr.
// Conflict-free B: lane tn reads col-pairs {tn, tn+16, tn+32, tn+48}.
// ---------------------------------------------------------------------------
#define ANS_G    141
#define NTILE_N  47
#define KSPLIT_W 672
#define KCH      21
#define REC_OFF  ((size_t)BATCH * 3 * VOC)
#define ANS_SLOT 15

__global__ void __launch_bounds__(256, 1)
answer_kernel(const float* __restrict__ xza,
              const float* __restrict__ Ua,
              const float* __restrict__ ba1,
              float* __restrict__ rec,
              float* __restrict__ hP, float* __restrict__ hQ,
              float* __restrict__ out) {
    extern __shared__ __align__(16) char asmem[];
    float* AsBuf = (float*)asmem;                               // 2*4160 floats
    ull*   BnBuf = (ull*)(asmem + 2 * 4160 * sizeof(float));    // 2*2048 ull
    ull*   BwBuf = BnBuf + 2 * 2048;                            // 2*2048 ull
    __shared__ float red[256];

    const int tid = threadIdx.x;
    const unsigned G = gridDim.x;
    unsigned sense = g_sns[ANS_SLOT * 32];

    for (int e = blockIdx.x * 256 + tid; e < BATCH * VOC; e += G * 256)
        hP[e] = 0.f;
    group_barrier(ANS_SLOT, G, sense);

    float* hp = hP;
    float* hn = hQ;

    const int ks    = blockIdx.x / NTILE_N;
    const int ntile = blockIdx.x - ks * NTILE_N;
    const int n0    = ntile * 128;
    const int kbase = ks * KSPLIT_W;
    float* recK = rec + (size_t)ks * REC_OFF;

    const int tm = tid >> 4;
    const int tn = tid & 15;

    for (int n = 0; n < NSENT; ++n) {
        // ================= phase A =================
        {
            ull aD[16], aX[16];
#pragma unroll
            for (int i = 0; i < 16; ++i) { aD[i] = 0ull; aX[i] = 0ull; }

            {
                const int k0 = kbase;
#pragma unroll
                for (int p = 0; p < 16; ++p) {
                    int e = p * 256 + tid;
                    int mm = e >> 5, kk = e & 31;
                    int k = k0 + kk;
                    AsBuf[kk * 130 + mm] = (k < VOC) ? hp[(size_t)mm * VOC + k] : 0.f;
                }
#pragma unroll
                for (int p = 0; p < 8; ++p) {
                    int e = p * 256 + tid;
                    int kk = e >> 6, np = e & 63;
                    int k = k0 + kk, nc = n0 + 2 * np;
                    float lo = 0.f, hi = 0.f;
                    if (k < VOC && nc < 3 * VOC) {
                        float2 v = *reinterpret_cast<const float2*>(&Ua[(size_t)k * (3 * VOC) + nc]);
                        lo = v.x; hi = v.y;
                    }
                    BnBuf[kk * 64 + np] = pack2(lo, hi);
                    BwBuf[kk * 64 + np] = pack2(hi, lo);
                }
            }

            int cur = 0;
            for (int ch = 0; ch < KCH; ++ch) {
                __syncthreads();
                if (ch + 1 < KCH) {
                    const int k0 = kbase + (ch + 1) * 32;
                    const int nb = cur ^ 1;
                    float* Asn = AsBuf + nb * 4160;
                    ull*   Bnn = BnBuf + nb * 2048;
                    ull*   Bwn = BwBuf + nb * 2048;
#pragma unroll
                    for (int p = 0; p < 16; ++p) {
                        int e = p * 256 + tid;
                        int mm = e >> 5, kk = e & 31;
                        int k = k0 + kk;
                        Asn[kk * 130 + mm] = (k < VOC) ? hp[(size_t)mm * VOC + k] : 0.f;
                    }
#pragma unroll
                    for (int p = 0; p < 8; ++p) {
                        int e = p * 256 + tid;
                        int kk = e >> 6, np = e & 63;
                        int k = k0 + kk, nc = n0 + 2 * np;
                        float lo = 0.f, hi = 0.f;
                        if (k < VOC && nc < 3 * VOC) {
                            float2 v = *reinterpret_cast<const float2*>(&Ua[(size_t)k * (3 * VOC) + nc]);
                            lo = v.x; hi = v.y;
                        }
                        Bnn[kk * 64 + np] = pack2(lo, hi);
                        Bwn[kk * 64 + np] = pack2(hi, lo);
                    }
                }
                const float* Asb = AsBuf + cur * 4160 + tm * 8;
                const ull*   Bnb = BnBuf + cur * 2048 + tn;
                const ull*   Bwb = BwBuf + cur * 2048 + tn;
#pragma unroll 4
                for (int kk = 0; kk < 32; ++kk) {
                    const float* ap = Asb + kk * 130;
                    ull a0 = *reinterpret_cast<const ull*>(ap + 0);
                    ull a1 = *reinterpret_cast<const ull*>(ap + 2);
                    ull a2 = *reinterpret_cast<const ull*>(ap + 4);
                    ull a3 = *reinterpret_cast<const ull*>(ap + 6);
                    const ull* bp = Bnb + kk * 64;
                    const ull* wp = Bwb + kk * 64;
                    ull b0 = bp[0],  b1 = bp[16], b2 = bp[32], b3 = bp[48];
                    ull w0 = wp[0],  w1 = wp[16], w2 = wp[32], w3 = wp[48];
                    fma2(aD[0],  a0, b0); fma2(aX[0],  a0, w0);
                    fma2(aD[1],  a0, b1); fma2(aX[1],  a0, w1);
                    fma2(aD[2],  a0, b2); fma2(aX[2],  a0, w2);
                    fma2(aD[3],  a0, b3); fma2(aX[3],  a0, w3);
                    fma2(aD[4],  a1, b0); fma2(aX[4],  a1, w0);
                    fma2(aD[5],  a1, b1); fma2(aX[5],  a1, w1);
                    fma2(aD[6],  a1, b2); fma2(aX[6],  a1, w2);
                    fma2(aD[7],  a1, b3); fma2(aX[7],  a1, w3);
                    fma2(aD[8],  a2, b0); fma2(aX[8],  a2, w0);
                    fma2(aD[9],  a2, b1); fma2(aX[9],  a2, w1);
                    fma2(aD[10], a2, b2); fma2(aX[10], a2, w2);
                    fma2(aD[11], a2, b3); fma2(aX[11], a2, w3);
                    fma2(aD[12], a3, b0); fma2(aX[12], a3, w0);
                    fma2(aD[13], a3, b1); fma2(aX[13], a3, w1);
                    fma2(aD[14], a3, b2); fma2(aX[14], a3, w2);
                    fma2(aD[15], a3, b3); fma2(aX[15], a3, w3);
                }
                cur ^= 1;
            }
            __syncthreads();
#pragma unroll
            for (int mi = 0; mi < 4; ++mi) {
#pragma unroll
                for (int ni = 0; ni < 4; ++ni) {
                    int m  = tm * 8 + 2 * mi;
                    int nc = n0 + 2 * (tn + 16 * ni);
                    if (nc < 3 * VOC) {
                        float2 d = unpack2(aD[mi * 4 + ni]);
                        float2 x = unpack2(aX[mi * 4 + ni]);
                        *reinterpret_cast<ull*>(&recK[(size_t)m * (3 * VOC) + nc]) = pack2(d.x, x.x);
                        *reinterpret_cast<ull*>(&recK[(size_t)(m + 1) * (3 * VOC) + nc]) = pack2(x.y, d.y);
                    }
                }
            }
        }
        group_barrier(ANS_SLOT, G, sense);

        // ================= phase B =================
        if (blockIdx.x < BATCH) {
            const int b = blockIdx.x;
            const float* xrow = xza + ((size_t)b * NSENT + n) * (3 * VOC);
            const float* r0 = rec + (size_t)b * (3 * VOC);
            const float* r1 = r0 + REC_OFF;
            const float* r2 = r1 + REC_OFF;
            float zv[8], tv[8];
            float m = -1e30f;
#pragma unroll
            for (int i = 0; i < 8; ++i) {
                int jj = tid + i * 256;
                if (jj < VOC) {
                    float Rz = r0[jj] + r1[jj] + r2[jj] + ba1[jj];
                    float Rr = r0[VOC + jj] + r1[VOC + jj] + r2[VOC + jj] + ba1[VOC + jj];
                    float Rh = r0[2 * VOC + jj] + r1[2 * VOC + jj] + r2[2 * VOC + jj] + ba1[2 * VOC + jj];
                    float z = sigmoidf_(xrow[jj] + Rz);
                    float r = sigmoidf_(xrow[VOC + jj] + Rr);
                    float t = xrow[2 * VOC + jj] + r * Rh;
                    zv[i] = z; tv[i] = t;
                    m = fmaxf(m, t);
                } else { zv[i] = 0.f; tv[i] = -1e30f; }
            }
            red[tid] = m; __syncthreads();
            for (int s = 128; s > 0; s >>= 1) {
                if (tid < s) red[tid] = fmaxf(red[tid], red[tid + s]);
                __syncthreads();
            }
            m = red[0]; __syncthreads();

            float ev[8];
            float sum = 0.f;
#pragma unroll
            for (int i = 0; i < 8; ++i) {
                int jj = tid + i * 256;
                if (jj < VOC) { ev[i] = expf(tv[i] - m); sum += ev[i]; }
                else ev[i] = 0.f;
            }
            red[tid] = sum; __syncthreads();
            for (int s = 128; s > 0; s >>= 1) {
                if (tid < s) red[tid] += red[tid + s];
                __syncthreads();
            }
            const float inv = 1.f / red[0];
            __syncthreads();

#pragma unroll
            for (int i = 0; i < 8; ++i) {
                int jj = tid + i * 256;
                if (jj < VOC) {
                    float hh = ev[i] * inv;
                    float z  = zv[i];
                    float hprev = hp[(size_t)b * VOC + jj];
                    float hnew = z * hprev + (1.f - z) * hh;
                    hn[(size_t)b * VOC + jj] = hnew;
                    out[((size_t)b * NSENT + n) * VOC + jj] = hnew;
                }
            }
        }
        group_barrier(ANS_SLOT, G, sense);
        float* tmp = hp; hp = hn; hn = tmp;
    }
}

// ---------------------------------------------------------------------------
// Host orchestration
// ---------------------------------------------------------------------------
extern "C" void kernel_launch(void* const* d_in, const int* in_sizes, int n_in,
                              void* d_out, int out_size) {
    const int*   info      = (const int*)d_in[0];
    const int*   info_idx  = (const int*)d_in[1];
    const int*   num_sent  = (const int*)d_in[2];
    const int*   question  = (const int*)d_in[3];
    const int*   qidx      = (const int*)d_in[4];
    const float* info_emb  = (const float*)d_in[5];
    const float* Wi        = (const float*)d_in[6];
    const float* Ui        = (const float*)d_in[7];
    const float* bi        = (const float*)d_in[8];
    const float* q_emb     = (const float*)d_in[9];
    const float* Wq        = (const float*)d_in[10];
    const float* Uq        = (const float*)d_in[11];
    const float* bq        = (const float*)d_in[12];
    const float* Wm        = (const float*)d_in[13];
    const float* Um        = (const float*)d_in[14];
    const float* bm        = (const float*)d_in[15];
    const float* Wa        = (const float*)d_in[16];
    const float* Ua        = (const float*)d_in[17];
    const float* ba        = (const float*)d_in[18];
    float* out = (float*)d_out;

    float *tbl_i, *tbl_q, *hinfo, *hq, *prod, *xzm, *hidden, *xza, *rec, *hA, *hB;
    cudaGetSymbolAddress((void**)&tbl_i, g_table_i);
    cudaGetSymbolAddress((void**)&tbl_q, g_table_q);
    cudaGetSymbolAddress((void**)&hinfo, g_hinfo);
    cudaGetSymbolAddress((void**)&hq, g_hq);
    cudaGetSymbolAddress((void**)&prod, g_prod);
    cudaGetSymbolAddress((void**)&xzm, g_xzm);
    cudaGetSymbolAddress((void**)&hidden, g_hidden);
    cudaGetSymbolAddress((void**)&xza, g_xza);
    cudaGetSymbolAddress((void**)&rec, g_rec);
    cudaGetSymbolAddress((void**)&hA, g_hA);
    cudaGetSymbolAddress((void**)&hB, g_hB);

    const size_t ansSmem = 2 * 4160 * sizeof(float) + 4 * 2048 * sizeof(ull);
    const size_t smemR = ((size_t)RUN * 48 + (size_t)16 * RUN) * 8;   // 204800
    const size_t smemM = ((size_t)MEM * 48 + (size_t)16 * MEM) * 8;   // 153600

    static bool attr_set = false;
    if (!attr_set) {
        cudaFuncSetAttribute(gru_seq_kernel<RUN>,
                             cudaFuncAttributeMaxDynamicSharedMemorySize, (int)smemR);
        cudaFuncSetAttribute(gru_seq_kernel<MEM>,
                             cudaFuncAttributeMaxDynamicSharedMemorySize, (int)smemM);
        cudaFuncSetAttribute(answer_kernel,
                             cudaFuncAttributeMaxDynamicSharedMemorySize, (int)ansSmem);
        attr_set = true;
    }

    stamp_kernel<<<1, 1>>>(0);

    build_table_kernel<<<dim3((3 * RUN + 255) / 256, 1024), 256>>>(info_emb, Wi, bi, tbl_i, 3 * RUN);
    build_table_kernel<<<dim3((3 * RUN + 255) / 256, 64), 256>>>(q_emb, Wq, bq, tbl_q, 3 * RUN);
    stamp_kernel<<<1, 1>>>(1);

    const dim3 blk(16, 8, 2);

    // info GRU (T=1024, H=400): 13x8 = 104 CTAs
    gru_seq_kernel<RUN><<<dim3((RUN + 31) / 32, 8), blk, smemR>>>(
        tbl_i, info, Ui, bi + 3 * RUN, hA, hB, hinfo, nullptr, SLEN);
    stamp_kernel<<<1, 1>>>(2);

    // question GRU (T=64, H=400)
    gru_seq_kernel<RUN><<<dim3((RUN + 31) / 32, 8), blk, smemR>>>(
        tbl_q, question, Uq, bq + 3 * RUN, hA, hB, hq, nullptr, QLEN);
    stamp_kernel<<<1, 1>>>(3);

    prod_kernel<<<dim3(NSENT, BATCH), 128>>>(hinfo, hq, info_idx, num_sent, qidx, prod);
    stamp_kernel<<<1, 1>>>(4);

    gemm_bias_kernel<<<dim3((3 * MEM + 63) / 64, (BATCH * NSENT) / 64), 256>>>(
        prod, Wm, bm, xzm, BATCH * NSENT, RUN, 3 * MEM);
    stamp_kernel<<<1, 1>>>(5);

    // memory GRU (T=64, H=300): 10x8 = 80 CTAs
    gru_seq_kernel<MEM><<<dim3((MEM + 31) / 32, 8), blk, smemM>>>(
        xzm, nullptr, Um, bm + 3 * MEM, hA, hB, hidden, num_sent, NSENT);
    stamp_kernel<<<1, 1>>>(6);

    gemm_bias_kernel<<<dim3((3 * VOC + 63) / 64, (BATCH * NSENT) / 64), 256>>>(
        hidden, Wa, ba, xza, BATCH * NSENT, MEM, 3 * VOC);
    stamp_kernel<<<1, 1>>>(7);

    answer_kernel<<<ANS_G, 256, ansSmem>>>(xza, Ua, ba + 3 * VOC, rec, hA, hB, out);
    stamp_kernel<<<1, 1>>>(8);

    report_kernel<<<1, 1>>>();
}

// round 8
// speedup vs baseline: 1.6272x; 1.0274x over previous
#include <cuda_runtime.h>
#include <cuda_bf16.h>
#include <cstdint>
#include <cstdio>

#define BATCH 128
#define SLEN  1024
#define NSENT 64
#define QLEN  64
#define EMB   50
#define RUN   400
#define MEM   300
#define VOC   2000

typedef unsigned long long ull;

__device__ __forceinline__ ull pack2(float lo, float hi) {
    ull r; asm("mov.b64 %0, {%1, %2};" : "=l"(r) : "f"(lo), "f"(hi)); return r;
}
__device__ __forceinline__ ull pdup(float v) { return pack2(v, v); }
__device__ __forceinline__ void fma2(ull& d, ull a, ull b) {
    asm("fma.rn.f32x2 %0, %1, %2, %0;" : "+l"(d) : "l"(a), "l"(b));
}
__device__ __forceinline__ void add2(ull& d, ull a) {
    asm("add.rn.f32x2 %0, %0, %1;" : "+l"(d) : "l"(a));
}
__device__ __forceinline__ float2 unpack2(ull v) {
    float2 r; asm("mov.b64 {%0, %1}, %2;" : "=f"(r.x), "=f"(r.y) : "l"(v)); return r;
}

// ---------------------------------------------------------------------------
// Device scratch
// ---------------------------------------------------------------------------
__device__ float g_table_i[1024 * 3 * RUN];
__device__ float g_table_q[64 * 3 * RUN];
__device__ float g_hinfo[(size_t)BATCH * SLEN * RUN];
__device__ float g_hq[(size_t)BATCH * QLEN * RUN];
__device__ float g_prod[(size_t)BATCH * NSENT * RUN];
__device__ float g_xzm[(size_t)BATCH * NSENT * 3 * MEM];
__device__ float g_hidden[(size_t)BATCH * NSENT * MEM];
__device__ float g_xza[(size_t)BATCH * NSENT * 3 * VOC];
__device__ float g_rec[(size_t)3 * BATCH * 3 * VOC];
__device__ float g_hA[(size_t)BATCH * VOC];
__device__ float g_hB[(size_t)BATCH * VOC];

// barrier state: 16 slots, each on its own 128B line
__device__ unsigned g_cnt[16 * 32];
__device__ volatile unsigned g_sns[16 * 32];

// phase timestamps (globaltimer ns)
__device__ unsigned long long g_ts[16];

__device__ __forceinline__ float sigmoidf_(float x) { return 1.f / (1.f + expf(-x)); }

// barrier over G CTAs sharing `slot`; pure spin
__device__ __forceinline__ void group_barrier(int slot, unsigned G, unsigned& sense) {
    __syncthreads();
    sense ^= 1u;
    if (threadIdx.x == 0 && threadIdx.y == 0 && threadIdx.z == 0) {
        __threadfence();
        unsigned prev = atomicAdd(&g_cnt[slot * 32], 1u);
        if (prev == G - 1u) {
            g_cnt[slot * 32] = 0u;
            __threadfence();
            g_sns[slot * 32] = sense;
        } else {
            while (g_sns[slot * 32] != sense) { }
        }
        __threadfence();
    }
    __syncthreads();
}

// ---------------------------------------------------------------------------
// timing stamps
// ---------------------------------------------------------------------------
__global__ void stamp_kernel(int i) {
    unsigned long long t;
    asm volatile("mov.u64 %0, %%globaltimer;" : "=l"(t));
    g_ts[i] = t;
}
__global__ void report_kernel() {
    printf("PHASES(us) tbl=%.0f info=%.0f q=%.0f prod=%.0f xzm=%.0f mem=%.0f xza=%.0f ans=%.0f\n",
           (g_ts[1] - g_ts[0]) * 1e-3, (g_ts[2] - g_ts[9]) * 1e-3,
           (g_ts[3] - g_ts[2]) * 1e-3, (g_ts[4] - g_ts[3]) * 1e-3,
           (g_ts[5] - g_ts[4]) * 1e-3, (g_ts[6] - g_ts[5]) * 1e-3,
           (g_ts[7] - g_ts[6]) * 1e-3, (g_ts[8] - g_ts[7]) * 1e-3);
}

// ---------------------------------------------------------------------------
// table[v, j] = sum_e emb[v,e] * W[e,j] + b0[j]
// ---------------------------------------------------------------------------
__global__ void build_table_kernel(const float* __restrict__ emb,
                                   const float* __restrict__ W,
                                   const float* __restrict__ b0,
                                   float* __restrict__ table,
                                   int N3) {
    int v = blockIdx.y;
    int j = blockIdx.x * blockDim.x + threadIdx.x;
    __shared__ float se[EMB];
    if (threadIdx.x < EMB) se[threadIdx.x] = emb[(size_t)v * EMB + threadIdx.x];
    __syncthreads();
    if (j < N3) {
        float acc = b0[j];
#pragma unroll 10
        for (int e = 0; e < EMB; ++e) acc += se[e] * W[(size_t)e * N3 + j];
        table[(size_t)v * N3 + j] = acc;
    }
}

// ---------------------------------------------------------------------------
// Persistent GRU, f32x2. block (16,4,2)=128 thr; tile 16 batch x 32 cols.
// thread (tx,ty,tz): rows 4ty..4ty+3, col-pair tx, k-half tz.
// Per k: 3 U LDS + 4 h LDS -> 12 FFMA2 (24 MAC). Gate xz inputs prefetched.
// ---------------------------------------------------------------------------
template <int H>
__global__ void __launch_bounds__(128, 1)
gru_seq_kernel(const float* __restrict__ xz,
               const int* __restrict__ tok,
               const float* __restrict__ U,
               const float* __restrict__ brec,
               float* __restrict__ hP, float* __restrict__ hQ,
               float* __restrict__ seq_out,
               const int* __restrict__ num_sent,
               int T) {
    extern __shared__ __align__(16) ull smu[];
    ull* su2 = smu;            // [H][48]
    ull* shd = smu + H * 48;   // [16][H]
    __shared__ ull sred[64 * 12];

    const int tx = threadIdx.x;   // 0..15 col-pair
    const int ty = threadIdx.y;   // 0..3 row-group (4 rows)
    const int tz = threadIdx.z;   // 0..1 k-split
    const int tid64 = ty * 16 + tx;
    const int tid = tz * 64 + tid64;
    const int j0 = blockIdx.x * 32;
    const int b0 = blockIdx.y * 16;
    const int N3 = 3 * H;
    const int slot = blockIdx.y;
    const unsigned G = gridDim.x;
    unsigned sense = g_sns[slot * 32];

    for (int e = tid; e < H * 48; e += 128) {
        int k = e / 48, c = e - k * 48;
        int g = c >> 4, p = c & 15;
        int j = j0 + 2 * p;
        float lo = (j < H) ? U[(size_t)k * N3 + g * H + j] : 0.f;
        float hi = (j + 1 < H) ? U[(size_t)k * N3 + g * H + j + 1] : 0.f;
        su2[e] = pack2(lo, hi);
    }
    for (int e = tid; e < 16 * 32; e += 128) {
        int bb = e >> 5, jj = e & 31;
        if (j0 + jj < H) hP[(size_t)(b0 + bb) * H + j0 + jj] = 0.f;
    }
    group_barrier(slot, G, sense);

    float* hp = hP;
    float* hn = hQ;

    const int jA = j0 + 2 * tx;
    const int jB = jA + 1;
    float bzA = 0, brA = 0, bhA = 0, bzB = 0, brB = 0, bhB = 0;
    if (jA < H) { bzA = brec[jA]; brA = brec[H + jA]; bhA = brec[2 * H + jA]; }
    if (jB < H) { bzB = brec[jB]; brB = brec[H + jB]; bhB = brec[2 * H + jB]; }

    constexpr int Hh = H / 2;
    const int kBeg = tz * Hh;
    const ull* up = su2 + tx;

    for (int t = 0; t < T; ++t) {
        // prefetch gate inputs (independent of staging) — tz==0 only
        ull xzp[4], xrp[4], xhp[4];
        int padi[4];
        if (tz == 0 && jA < H) {
#pragma unroll
            for (int r = 0; r < 4; ++r) {
                const int b = b0 + 4 * ty + r;
                const float* xrow;
                if (tok) xrow = xz + (size_t)tok[(size_t)b * T + t] * N3;
                else     xrow = xz + ((size_t)b * T + t) * N3;
                xzp[r] = *reinterpret_cast<const ull*>(xrow + jA);
                xrp[r] = *reinterpret_cast<const ull*>(xrow + H + jA);
                xhp[r] = *reinterpret_cast<const ull*>(xrow + 2 * H + jA);
                padi[r] = num_sent ? num_sent[b] : 0x7fffffff;
            }
        }

        // stage h_prev rows, duplicated
        for (int e = tid; e < 16 * H; e += 128) {
            int row = e / H, k = e - row * H;
            shd[row * H + k] = pdup(hp[(size_t)(b0 + row) * H + k]);
        }
        __syncthreads();

        ull az[4] = {0,0,0,0}, ar[4] = {0,0,0,0}, ah[4] = {0,0,0,0};
        const ull* h0p = shd + (4 * ty + 0) * H + kBeg;
        const ull* h1p = shd + (4 * ty + 1) * H + kBeg;
        const ull* h2p = shd + (4 * ty + 2) * H + kBeg;
        const ull* h3p = shd + (4 * ty + 3) * H + kBeg;
        const ull* ub = up + kBeg * 48;
#pragma unroll 4
        for (int kk = 0; kk < Hh; ++kk) {
            ull uz = ub[kk * 48];
            ull ur = ub[kk * 48 + 16];
            ull uh = ub[kk * 48 + 32];
            ull h0 = h0p[kk], h1 = h1p[kk], h2 = h2p[kk], h3 = h3p[kk];
            fma2(az[0], h0, uz); fma2(az[1], h1, uz); fma2(az[2], h2, uz); fma2(az[3], h3, uz);
            fma2(ar[0], h0, ur); fma2(ar[1], h1, ur); fma2(ar[2], h2, ur); fma2(ar[3], h3, ur);
            fma2(ah[0], h0, uh); fma2(ah[1], h1, uh); fma2(ah[2], h2, uh); fma2(ah[3], h3, uh);
        }

        if (tz == 1) {
            ull* s = sred + tid64 * 12;
#pragma unroll
            for (int r = 0; r < 4; ++r) { s[r] = az[r]; s[4 + r] = ar[r]; s[8 + r] = ah[r]; }
        }
        __syncthreads();

        if (tz == 0) {
            const ull* s = sred + tid64 * 12;
#pragma unroll
            for (int r = 0; r < 4; ++r) { add2(az[r], s[r]); add2(ar[r], s[4 + r]); add2(ah[r], s[8 + r]); }

            if (jA < H) {
#pragma unroll
                for (int r = 0; r < 4; ++r) {
                    const int row = 4 * ty + r;
                    const int b = b0 + row;
                    float2 AZ = unpack2(az[r]);
                    float2 AR = unpack2(ar[r]);
                    float2 AH = unpack2(ah[r]);
                    float2 XZ = unpack2(xzp[r]);
                    float2 XR = unpack2(xrp[r]);
                    float2 XH = unpack2(xhp[r]);
                    float padv = (t <= padi[r]) ? 1.f : 0.f;
                    {
                        float z  = sigmoidf_(XZ.x + AZ.x + bzA);
                        float rr = sigmoidf_(XR.x + AR.x + brA);
                        float hh = tanhf(XH.x + rr * (AH.x + bhA));
                        float hprev = unpack2(shd[row * H + jA]).x;
                        float hnew = z * hprev + (1.f - z) * hh;
                        hn[(size_t)b * H + jA] = hnew;
                        seq_out[((size_t)b * T + t) * H + jA] = hnew * padv;
                    }
                    if (jB < H) {
                        float z  = sigmoidf_(XZ.y + AZ.y + bzB);
                        float rr = sigmoidf_(XR.y + AR.y + brB);
                        float hh = tanhf(XH.y + rr * (AH.y + bhB));
                        float hprev = unpack2(shd[row * H + jB]).x;
                        float hnew = z * hprev + (1.f - z) * hh;
                        hn[(size_t)b * H + jB] = hnew;
                        seq_out[((size_t)b * T + t) * H + jB] = hnew * padv;
                    }
                }
            }
        }
        group_barrier(slot, G, sense);
        float* tmp = hp; hp = hn; hn = tmp;
    }
}

// ---------------------------------------------------------------------------
// prod
// ---------------------------------------------------------------------------
__global__ void prod_kernel(const float* __restrict__ hinfo,
                            const float* __restrict__ hq,
                            const int* __restrict__ info_idx,
                            const int* __restrict__ num_sent,
                            const int* __restrict__ qidx,
                            float* __restrict__ prod) {
    const int nn = blockIdx.x;
    const int b  = blockIdx.y;
    const int si = info_idx[b * NSENT + nn];
    const int qi = qidx[b] - 1;
    const float padv = (nn <= num_sent[b]) ? 1.f : 0.f;
    const float* hi  = hinfo + ((size_t)b * SLEN + si) * RUN;
    const float* hqr = hq + ((size_t)b * QLEN + qi) * RUN;
    float* pr = prod + ((size_t)b * NSENT + nn) * RUN;
    for (int jj = threadIdx.x; jj < RUN; jj += blockDim.x)
        pr[jj] = hi[jj] * hqr[jj] * padv;
}

// ---------------------------------------------------------------------------
// Generic C = A@W + bias, 64x64 tile, BK=16, 4x4/thread. (xzm, xza)
// ---------------------------------------------------------------------------
__global__ void gemm_bias_kernel(const float* __restrict__ A,
                                 const float* __restrict__ W,
                                 const float* __restrict__ bias,
                                 float* __restrict__ C,
                                 int Mdim, int Kdim, int Ndim) {
    __shared__ __align__(16) float As[16][68];
    __shared__ __align__(16) float Bs[16][68];
    const int tid = threadIdx.x;
    const int tx = tid & 15;
    const int ty = tid >> 4;
    const int m0 = blockIdx.y * 64;
    const int n0 = blockIdx.x * 64;

    float acc[4][4];
#pragma unroll
    for (int i = 0; i < 4; ++i)
#pragma unroll
        for (int jj = 0; jj < 4; ++jj) acc[i][jj] = 0.f;

    for (int k0 = 0; k0 < Kdim; k0 += 16) {
        for (int e = tid; e < 1024; e += 256) {
            int mm = e >> 4, kk = e & 15;
            int m = m0 + mm, k = k0 + kk;
            As[kk][mm] = (m < Mdim && k < Kdim) ? A[(size_t)m * Kdim + k] : 0.f;
        }
        for (int e = tid; e < 1024; e += 256) {
            int kk = e >> 6, nn = e & 63;
            int k = k0 + kk, nv = n0 + nn;
            Bs[kk][nn] = (k < Kdim && nv < Ndim) ? W[(size_t)k * Ndim + nv] : 0.f;
        }
        __syncthreads();
#pragma unroll
        for (int kk = 0; kk < 16; ++kk) {
            float4 a4 = *reinterpret_cast<const float4*>(&As[kk][ty * 4]);
            float4 b4 = *reinterpret_cast<const float4*>(&Bs[kk][tx * 4]);
            float av[4] = {a4.x, a4.y, a4.z, a4.w};
            float bv[4] = {b4.x, b4.y, b4.z, b4.w};
#pragma unroll
            for (int i = 0; i < 4; ++i)
#pragma unroll
                for (int jj = 0; jj < 4; ++jj) acc[i][jj] += av[i] * bv[jj];
        }
        __syncthreads();
    }
#pragma unroll
    for (int i = 0; i < 4; ++i) {
        int m = m0 + ty * 4 + i;
        if (m >= Mdim) continue;
#pragma unroll
        for (int jj = 0; jj < 4; ++jj) {
            int nv = n0 + tx * 4 + jj;
            if (nv < Ndim) C[(size_t)m * Ndim + nv] = acc[i][jj] + bias[nv];
        }
    }
}

// ---------------------------------------------------------------------------
// Persistent answer GRU (r7 form). grid = 141 CTAs, 256 thr.
// ---------------------------------------------------------------------------
#define ANS_G    141
#define NTILE_N  47
#define KSPLIT_W 672
#define KCH      21
#define REC_OFF  ((size_t)BATCH * 3 * VOC)
#define ANS_SLOT 15

__global__ void __launch_bounds__(256, 1)
answer_kernel(const float* __restrict__ xza,
              const float* __restrict__ Ua,
              const float* __restrict__ ba1,
              float* __restrict__ rec,
              float* __restrict__ hP, float* __restrict__ hQ,
              float* __restrict__ out) {
    extern __shared__ __align__(16) char asmem[];
    float* AsBuf = (float*)asmem;
    ull*   BnBuf = (ull*)(asmem + 2 * 4160 * sizeof(float));
    ull*   BwBuf = BnBuf + 2 * 2048;
    __shared__ float red[256];

    const int tid = threadIdx.x;
    const unsigned G = gridDim.x;
    unsigned sense = g_sns[ANS_SLOT * 32];

    for (int e = blockIdx.x * 256 + tid; e < BATCH * VOC; e += G * 256)
        hP[e] = 0.f;
    group_barrier(ANS_SLOT, G, sense);

    float* hp = hP;
    float* hn = hQ;

    const int ks    = blockIdx.x / NTILE_N;
    const int ntile = blockIdx.x - ks * NTILE_N;
    const int n0    = ntile * 128;
    const int kbase = ks * KSPLIT_W;
    float* recK = rec + (size_t)ks * REC_OFF;

    const int tm = tid >> 4;
    const int tn = tid & 15;

    for (int n = 0; n < NSENT; ++n) {
        // ================= phase A =================
        {
            ull aD[16], aX[16];
#pragma unroll
            for (int i = 0; i < 16; ++i) { aD[i] = 0ull; aX[i] = 0ull; }

            {
                const int k0 = kbase;
#pragma unroll
                for (int p = 0; p < 16; ++p) {
                    int e = p * 256 + tid;
                    int mm = e >> 5, kk = e & 31;
                    int k = k0 + kk;
                    AsBuf[kk * 130 + mm] = (k < VOC) ? hp[(size_t)mm * VOC + k] : 0.f;
                }
#pragma unroll
                for (int p = 0; p < 8; ++p) {
                    int e = p * 256 + tid;
                    int kk = e >> 6, np = e & 63;
                    int k = k0 + kk, nc = n0 + 2 * np;
                    float lo = 0.f, hi = 0.f;
                    if (k < VOC && nc < 3 * VOC) {
                        float2 v = *reinterpret_cast<const float2*>(&Ua[(size_t)k * (3 * VOC) + nc]);
                        lo = v.x; hi = v.y;
                    }
                    BnBuf[kk * 64 + np] = pack2(lo, hi);
                    BwBuf[kk * 64 + np] = pack2(hi, lo);
                }
            }

            int cur = 0;
            for (int ch = 0; ch < KCH; ++ch) {
                __syncthreads();
                if (ch + 1 < KCH) {
                    const int k0 = kbase + (ch + 1) * 32;
                    const int nb = cur ^ 1;
                    float* Asn = AsBuf + nb * 4160;
                    ull*   Bnn = BnBuf + nb * 2048;
                    ull*   Bwn = BwBuf + nb * 2048;
#pragma unroll
                    for (int p = 0; p < 16; ++p) {
                        int e = p * 256 + tid;
                        int mm = e >> 5, kk = e & 31;
                        int k = k0 + kk;
                        Asn[kk * 130 + mm] = (k < VOC) ? hp[(size_t)mm * VOC + k] : 0.f;
                    }
#pragma unroll
                    for (int p = 0; p < 8; ++p) {
                        int e = p * 256 + tid;
                        int kk = e >> 6, np = e & 63;
                        int k = k0 + kk, nc = n0 + 2 * np;
                        float lo = 0.f, hi = 0.f;
                        if (k < VOC && nc < 3 * VOC) {
                            float2 v = *reinterpret_cast<const float2*>(&Ua[(size_t)k * (3 * VOC) + nc]);
                            lo = v.x; hi = v.y;
                        }
                        Bnn[kk * 64 + np] = pack2(lo, hi);
                        Bwn[kk * 64 + np] = pack2(hi, lo);
                    }
                }
                const float* Asb = AsBuf + cur * 4160 + tm * 8;
                const ull*   Bnb = BnBuf + cur * 2048 + tn;
                const ull*   Bwb = BwBuf + cur * 2048 + tn;
#pragma unroll 4
                for (int kk = 0; kk < 32; ++kk) {
                    const float* ap = Asb + kk * 130;
                    ull a0 = *reinterpret_cast<const ull*>(ap + 0);
                    ull a1 = *reinterpret_cast<const ull*>(ap + 2);
                    ull a2 = *reinterpret_cast<const ull*>(ap + 4);
                    ull a3 = *reinterpret_cast<const ull*>(ap + 6);
                    const ull* bp = Bnb + kk * 64;
                    const ull* wp = Bwb + kk * 64;
                    ull b0 = bp[0],  b1 = bp[16], b2 = bp[32], b3 = bp[48];
                    ull w0 = wp[0],  w1 = wp[16], w2 = wp[32], w3 = wp[48];
                    fma2(aD[0],  a0, b0); fma2(aX[0],  a0, w0);
                    fma2(aD[1],  a0, b1); fma2(aX[1],  a0, w1);
                    fma2(aD[2],  a0, b2); fma2(aX[2],  a0, w2);
                    fma2(aD[3],  a0, b3); fma2(aX[3],  a0, w3);
                    fma2(aD[4],  a1, b0); fma2(aX[4],  a1, w0);
                    fma2(aD[5],  a1, b1); fma2(aX[5],  a1, w1);
                    fma2(aD[6],  a1, b2); fma2(aX[6],  a1, w2);
                    fma2(aD[7],  a1, b3); fma2(aX[7],  a1, w3);
                    fma2(aD[8],  a2, b0); fma2(aX[8],  a2, w0);
                    fma2(aD[9],  a2, b1); fma2(aX[9],  a2, w1);
                    fma2(aD[10], a2, b2); fma2(aX[10], a2, w2);
                    fma2(aD[11], a2, b3); fma2(aX[11], a2, w3);
                    fma2(aD[12], a3, b0); fma2(aX[12], a3, w0);
                    fma2(aD[13], a3, b1); fma2(aX[13], a3, w1);
                    fma2(aD[14], a3, b2); fma2(aX[14], a3, w2);
                    fma2(aD[15], a3, b3); fma2(aX[15], a3, w3);
                }
                cur ^= 1;
            }
            __syncthreads();
#pragma unroll
            for (int mi = 0; mi < 4; ++mi) {
#pragma unroll
                for (int ni = 0; ni < 4; ++ni) {
                    int m  = tm * 8 + 2 * mi;
                    int nc = n0 + 2 * (tn + 16 * ni);
                    if (nc < 3 * VOC) {
                        float2 d = unpack2(aD[mi * 4 + ni]);
                        float2 x = unpack2(aX[mi * 4 + ni]);
                        *reinterpret_cast<ull*>(&recK[(size_t)m * (3 * VOC) + nc]) = pack2(d.x, x.x);
                        *reinterpret_cast<ull*>(&recK[(size_t)(m + 1) * (3 * VOC) + nc]) = pack2(x.y, d.y);
                    }
                }
            }
        }
        group_barrier(ANS_SLOT, G, sense);

        // ================= phase B =================
        if (blockIdx.x < BATCH) {
            const int b = blockIdx.x;
            const float* xrow = xza + ((size_t)b * NSENT + n) * (3 * VOC);
            const float* r0 = rec + (size_t)b * (3 * VOC);
            const float* r1 = r0 + REC_OFF;
            const float* r2 = r1 + REC_OFF;
            float zv[8], tv[8];
            float m = -1e30f;
#pragma unroll
            for (int i = 0; i < 8; ++i) {
                int jj = tid + i * 256;
                if (jj < VOC) {
                    float Rz = r0[jj] + r1[jj] + r2[jj] + ba1[jj];
                    float Rr = r0[VOC + jj] + r1[VOC + jj] + r2[VOC + jj] + ba1[VOC + jj];
                    float Rh = r0[2 * VOC + jj] + r1[2 * VOC + jj] + r2[2 * VOC + jj] + ba1[2 * VOC + jj];
                    float z = sigmoidf_(xrow[jj] + Rz);
                    float r = sigmoidf_(xrow[VOC + jj] + Rr);
                    float t = xrow[2 * VOC + jj] + r * Rh;
                    zv[i] = z; tv[i] = t;
                    m = fmaxf(m, t);
                } else { zv[i] = 0.f; tv[i] = -1e30f; }
            }
            red[tid] = m; __syncthreads();
            for (int s = 128; s > 0; s >>= 1) {
                if (tid < s) red[tid] = fmaxf(red[tid], red[tid + s]);
                __syncthreads();
            }
            m = red[0]; __syncthreads();

            float ev[8];
            float sum = 0.f;
#pragma unroll
            for (int i = 0; i < 8; ++i) {
                int jj = tid + i * 256;
                if (jj < VOC) { ev[i] = expf(tv[i] - m); sum += ev[i]; }
                else ev[i] = 0.f;
            }
            red[tid] = sum; __syncthreads();
            for (int s = 128; s > 0; s >>= 1) {
                if (tid < s) red[tid] += red[tid + s];
                __syncthreads();
            }
            const float inv = 1.f / red[0];
            __syncthreads();

#pragma unroll
            for (int i = 0; i < 8; ++i) {
                int jj = tid + i * 256;
                if (jj < VOC) {
                    float hh = ev[i] * inv;
                    float z  = zv[i];
                    float hprev = hp[(size_t)b * VOC + jj];
                    float hnew = z * hprev + (1.f - z) * hh;
                    hn[(size_t)b * VOC + jj] = hnew;
                    out[((size_t)b * NSENT + n) * VOC + jj] = hnew;
                }
            }
        }
        group_barrier(ANS_SLOT, G, sense);
        float* tmp = hp; hp = hn; hn = tmp;
    }
}

// ---------------------------------------------------------------------------
// Host orchestration. Launch order puts info-GRU at launch #6 so
// ncu -s 5 -c 1 profiles it.
// ---------------------------------------------------------------------------
extern "C" void kernel_launch(void* const* d_in, const int* in_sizes, int n_in,
                              void* d_out, int out_size) {
    const int*   info      = (const int*)d_in[0];
    const int*   info_idx  = (const int*)d_in[1];
    const int*   num_sent  = (const int*)d_in[2];
    const int*   question  = (const int*)d_in[3];
    const int*   qidx      = (const int*)d_in[4];
    const float* info_emb  = (const float*)d_in[5];
    const float* Wi        = (const float*)d_in[6];
    const float* Ui        = (const float*)d_in[7];
    const float* bi        = (const float*)d_in[8];
    const float* q_emb     = (const float*)d_in[9];
    const float* Wq        = (const float*)d_in[10];
    const float* Uq        = (const float*)d_in[11];
    const float* bq        = (const float*)d_in[12];
    const float* Wm        = (const float*)d_in[13];
    const float* Um        = (const float*)d_in[14];
    const float* bm        = (const float*)d_in[15];
    const float* Wa        = (const float*)d_in[16];
    const float* Ua        = (const float*)d_in[17];
    const float* ba        = (const float*)d_in[18];
    float* out = (float*)d_out;

    float *tbl_i, *tbl_q, *hinfo, *hq, *prod, *xzm, *hidden, *xza, *rec, *hA, *hB;
    cudaGetSymbolAddress((void**)&tbl_i, g_table_i);
    cudaGetSymbolAddress((void**)&tbl_q, g_table_q);
    cudaGetSymbolAddress((void**)&hinfo, g_hinfo);
    cudaGetSymbolAddress((void**)&hq, g_hq);
    cudaGetSymbolAddress((void**)&prod, g_prod);
    cudaGetSymbolAddress((void**)&xzm, g_xzm);
    cudaGetSymbolAddress((void**)&hidden, g_hidden);
    cudaGetSymbolAddress((void**)&xza, g_xza);
    cudaGetSymbolAddress((void**)&rec, g_rec);
    cudaGetSymbolAddress((void**)&hA, g_hA);
    cudaGetSymbolAddress((void**)&hB, g_hB);

    const size_t ansSmem = 2 * 4160 * sizeof(float) + 4 * 2048 * sizeof(ull);
    const size_t smemR = ((size_t)RUN * 48 + (size_t)16 * RUN) * 8;   // 204800
    const size_t smemM = ((size_t)MEM * 48 + (size_t)16 * MEM) * 8;   // 153600

    static bool attr_set = false;
    if (!attr_set) {
        cudaFuncSetAttribute(gru_seq_kernel<RUN>,
                             cudaFuncAttributeMaxDynamicSharedMemorySize, (int)smemR);
        cudaFuncSetAttribute(gru_seq_kernel<MEM>,
                             cudaFuncAttributeMaxDynamicSharedMemorySize, (int)smemM);
        cudaFuncSetAttribute(answer_kernel,
                             cudaFuncAttributeMaxDynamicSharedMemorySize, (int)ansSmem);
        attr_set = true;
    }

    const dim3 blk(16, 4, 2);

    // launches 1-2
    build_table_kernel<<<dim3((3 * RUN + 255) / 256, 1024), 256>>>(info_emb, Wi, bi, tbl_i, 3 * RUN);
    build_table_kernel<<<dim3((3 * RUN + 255) / 256, 64), 256>>>(q_emb, Wq, bq, tbl_q, 3 * RUN);
    // launches 3-5 (stamps; ncu -s 5 skips these + tables)
    stamp_kernel<<<1, 1>>>(0);
    stamp_kernel<<<1, 1>>>(1);
    stamp_kernel<<<1, 1>>>(9);

    // launch 6: info GRU (T=1024, H=400) — profiled by ncu
    gru_seq_kernel<RUN><<<dim3((RUN + 31) / 32, 8), blk, smemR>>>(
        tbl_i, info, Ui, bi + 3 * RUN, hA, hB, hinfo, nullptr, SLEN);
    stamp_kernel<<<1, 1>>>(2);

    // question GRU (T=64, H=400)
    gru_seq_kernel<RUN><<<dim3((RUN + 31) / 32, 8), blk, smemR>>>(
        tbl_q, question, Uq, bq + 3 * RUN, hA, hB, hq, nullptr, QLEN);
    stamp_kernel<<<1, 1>>>(3);

    prod_kernel<<<dim3(NSENT, BATCH), 128>>>(hinfo, hq, info_idx, num_sent, qidx, prod);
    stamp_kernel<<<1, 1>>>(4);

    gemm_bias_kernel<<<dim3((3 * MEM + 63) / 64, (BATCH * NSENT) / 64), 256>>>(
        prod, Wm, bm, xzm, BATCH * NSENT, RUN, 3 * MEM);
    stamp_kernel<<<1, 1>>>(5);

    // memory GRU (T=64, H=300)
    gru_seq_kernel<MEM><<<dim3((MEM + 31) / 32, 8), blk, smemM>>>(
        xzm, nullptr, Um, bm + 3 * MEM, hA, hB, hidden, num_sent, NSENT);
    stamp_kernel<<<1, 1>>>(6);

    gemm_bias_kernel<<<dim3((3 * VOC + 63) / 64, (BATCH * NSENT) / 64), 256>>>(
        hidden, Wa, ba, xza, BATCH * NSENT, MEM, 3 * VOC);
    stamp_kernel<<<1, 1>>>(7);

    answer_kernel<<<ANS_G, 256, ansSmem>>>(xza, Ua, ba + 3 * VOC, rec, hA, hB, out);
    stamp_kernel<<<1, 1>>>(8);

    report_kernel<<<1, 1>>>();
}